// round 1
// baseline (speedup 1.0000x reference)
#include <cuda_runtime.h>

#define BB 4
#define DM 256
#define NN 2048
#define HH 4
#define HD 64

// Scratch (device globals — no runtime allocation allowed)
__device__ float g_q[BB * HH * NN * HD];   // [b*H+h][n][d]
__device__ float g_k[BB * HH * NN * HD];
__device__ float g_v[BB * HH * NN * HD];
__device__ float g_x[BB * DM * NN];        // attention out, [b][c][n], c = d*H+h

// ---------------------------------------------------------------------------
// QKV projection: out[c,n] = sum_i W[c,i] * x[b,i,n] + bias[c]
// 64x64 output tile per block, 16x16 threads, 4x4 per-thread microtile.
// Epilogue stages through SMEM and writes [b,h,n,d] layout coalesced.
// ---------------------------------------------------------------------------
__global__ __launch_bounds__(256) void qkv_proj_kernel(
    const float* __restrict__ qin, const float* __restrict__ kin,
    const float* __restrict__ vin,
    const float* __restrict__ Wq, const float* __restrict__ bq,
    const float* __restrict__ Wk, const float* __restrict__ bk,
    const float* __restrict__ Wv, const float* __restrict__ bv)
{
    __shared__ float Wt[32 * 65];   // [kk][o], padded
    __shared__ float Xs[32 * 64];   // [kk][n]
    __shared__ float Stg[64 * 65];  // epilogue staging [c_local][n_local]

    const int tx = threadIdx.x, ty = threadIdx.y;
    const int tid = ty * 16 + tx;
    const int z = blockIdx.z;
    const int which = z >> 2, b = z & 3;

    const float* X; const float* W; const float* bias; float* dst;
    if (which == 0)      { X = qin; W = Wq; bias = bq; dst = g_q; }
    else if (which == 1) { X = kin; W = Wk; bias = bk; dst = g_k; }
    else                 { X = vin; W = Wv; bias = bv; dst = g_v; }

    const int o0 = blockIdx.y * 64;
    const int n0 = blockIdx.x * 64;
    const float* Xb = X + (size_t)b * DM * NN;

    float acc[4][4];
    #pragma unroll
    for (int i = 0; i < 4; i++)
        #pragma unroll
        for (int j = 0; j < 4; j++) acc[i][j] = 0.f;

    for (int k0 = 0; k0 < DM; k0 += 32) {
        #pragma unroll
        for (int it = 0; it < 2; it++) {
            int t = tid + it * 256;
            // W tile: 64 o x 32 kk, transposed into Wt[kk][o]
            int o = t >> 3, kk4 = (t & 7) << 2;
            float4 w4 = *(const float4*)(W + (size_t)(o0 + o) * DM + k0 + kk4);
            Wt[(kk4 + 0) * 65 + o] = w4.x;
            Wt[(kk4 + 1) * 65 + o] = w4.y;
            Wt[(kk4 + 2) * 65 + o] = w4.z;
            Wt[(kk4 + 3) * 65 + o] = w4.w;
            // X tile: 32 kk x 64 n
            int r = t >> 4, c4 = (t & 15) << 2;
            *(float4*)&Xs[r * 64 + c4] =
                *(const float4*)(Xb + (size_t)(k0 + r) * NN + n0 + c4);
        }
        __syncthreads();
        #pragma unroll 8
        for (int kk = 0; kk < 32; kk++) {
            float w0 = Wt[kk * 65 + 4 * ty + 0];
            float w1 = Wt[kk * 65 + 4 * ty + 1];
            float w2 = Wt[kk * 65 + 4 * ty + 2];
            float w3 = Wt[kk * 65 + 4 * ty + 3];
            float4 xv = *(const float4*)&Xs[kk * 64 + 4 * tx];
            acc[0][0] += w0 * xv.x; acc[0][1] += w0 * xv.y; acc[0][2] += w0 * xv.z; acc[0][3] += w0 * xv.w;
            acc[1][0] += w1 * xv.x; acc[1][1] += w1 * xv.y; acc[1][2] += w1 * xv.z; acc[1][3] += w1 * xv.w;
            acc[2][0] += w2 * xv.x; acc[2][1] += w2 * xv.y; acc[2][2] += w2 * xv.z; acc[2][3] += w2 * xv.w;
            acc[3][0] += w3 * xv.x; acc[3][1] += w3 * xv.y; acc[3][2] += w3 * xv.z; acc[3][3] += w3 * xv.w;
        }
        __syncthreads();
    }

    // Stage to shared, then write [b,h,n,d] layout with coalesced stores.
    #pragma unroll
    for (int i = 0; i < 4; i++) {
        float bv_ = bias[o0 + 4 * ty + i];
        #pragma unroll
        for (int j = 0; j < 4; j++)
            Stg[(4 * ty + i) * 65 + 4 * tx + j] = acc[i][j] + bv_;
    }
    __syncthreads();
    #pragma unroll
    for (int it = 0; it < 16; it++) {
        int t = tid + it * 256;
        int dl = t & 15;            // local d (16 per 64-channel tile)
        int nl = (t >> 4) & 63;     // local n
        int h  = t >> 10;           // head
        float v = Stg[(dl * 4 + h) * 65 + nl];
        dst[(((size_t)(b * HH + h)) * NN + n0 + nl) * HD + (o0 >> 2) + dl] = v;
    }
}

// ---------------------------------------------------------------------------
// RoPE on q and k in-place: pairs (2j, 2j+1) rotated with per-(n,d) cos/sin
// ---------------------------------------------------------------------------
__global__ __launch_bounds__(256) void rope_kernel(const float* __restrict__ enc)
{
    int idx = blockIdx.x * blockDim.x + threadIdx.x;  // BB*HH*NN*32 threads
    int p  = idx & 31;
    int n  = (idx >> 5) & (NN - 1);
    int bh = idx >> 16;

    float2 c2 = *(const float2*)(enc + (size_t)n * HD + 2 * p);
    float2 s2 = *(const float2*)(enc + (size_t)NN * HD + (size_t)n * HD + 2 * p);
    size_t base = ((size_t)bh * NN + n) * HD + 2 * p;

    float2 qv = *(float2*)(g_q + base);
    float2 kv = *(float2*)(g_k + base);
    float2 qo, ko;
    qo.x = qv.x * c2.x - qv.y * s2.x;
    qo.y = qv.y * c2.y + qv.x * s2.y;
    ko.x = kv.x * c2.x - kv.y * s2.x;
    ko.y = kv.y * c2.y + kv.x * s2.y;
    *(float2*)(g_q + base) = qo;
    *(float2*)(g_k + base) = ko;
}

// ---------------------------------------------------------------------------
// Flash-attention style: per (b,h), 64 query rows per block, loop over 64-wide
// K/V tiles with online softmax. 16x16 threads, 4x4 microtiles for both GEMMs.
// ---------------------------------------------------------------------------
#define ATTN_SMEM_FLOATS (3 * 64 * 65 + 64 * 64)
#define ATTN_SMEM_BYTES  (ATTN_SMEM_FLOATS * 4)

__global__ __launch_bounds__(256) void attn_kernel()
{
    extern __shared__ float sm[];
    float* Qs  = sm;                // [r][dd] padded 65 (pre-scaled by 1/8)
    float* Kst = sm + 64 * 65;      // [dd][c] padded 65
    float* Ps  = sm + 2 * 64 * 65;  // [r][m]  padded 65
    float* Vs  = sm + 3 * 64 * 65;  // [m][dd] unpadded (float4 row reads)

    const int tx = threadIdx.x, ty = threadIdx.y;
    const int tid = ty * 16 + tx;
    const int bh = blockIdx.y;
    const int n0 = blockIdx.x * 64;
    const size_t base_bh = (size_t)bh * NN * HD;

    // Load Q tile, pre-scaled by 1/sqrt(64)
    #pragma unroll
    for (int it = 0; it < 4; it++) {
        int t = tid + it * 256;
        int r = t >> 4, d4 = (t & 15) << 2;
        float4 q4 = *(const float4*)(g_q + base_bh + (size_t)(n0 + r) * HD + d4);
        Qs[r * 65 + d4 + 0] = q4.x * 0.125f;
        Qs[r * 65 + d4 + 1] = q4.y * 0.125f;
        Qs[r * 65 + d4 + 2] = q4.z * 0.125f;
        Qs[r * 65 + d4 + 3] = q4.w * 0.125f;
    }

    float acc[4][4];
    float mrow[4], lrow[4];
    #pragma unroll
    for (int i = 0; i < 4; i++) {
        mrow[i] = -1e30f; lrow[i] = 0.f;
        #pragma unroll
        for (int j = 0; j < 4; j++) acc[i][j] = 0.f;
    }

    for (int m0 = 0; m0 < NN; m0 += 64) {
        __syncthreads();  // prior PV reads done before overwriting K/V
        #pragma unroll
        for (int it = 0; it < 4; it++) {
            int t = tid + it * 256;
            int c = t >> 4, d4 = (t & 15) << 2;
            float4 k4 = *(const float4*)(g_k + base_bh + (size_t)(m0 + c) * HD + d4);
            Kst[(d4 + 0) * 65 + c] = k4.x;
            Kst[(d4 + 1) * 65 + c] = k4.y;
            Kst[(d4 + 2) * 65 + c] = k4.z;
            Kst[(d4 + 3) * 65 + c] = k4.w;
            float4 v4 = *(const float4*)(g_v + base_bh + (size_t)(m0 + c) * HD + d4);
            *(float4*)&Vs[c * 64 + d4] = v4;
        }
        __syncthreads();

        // S = Q K^T (already scaled)
        float s[4][4];
        #pragma unroll
        for (int i = 0; i < 4; i++)
            #pragma unroll
            for (int j = 0; j < 4; j++) s[i][j] = 0.f;

        #pragma unroll 16
        for (int dd = 0; dd < 64; dd++) {
            float qv0 = Qs[(4 * ty + 0) * 65 + dd];
            float qv1 = Qs[(4 * ty + 1) * 65 + dd];
            float qv2 = Qs[(4 * ty + 2) * 65 + dd];
            float qv3 = Qs[(4 * ty + 3) * 65 + dd];
            float kv0 = Kst[dd * 65 + 4 * tx + 0];
            float kv1 = Kst[dd * 65 + 4 * tx + 1];
            float kv2 = Kst[dd * 65 + 4 * tx + 2];
            float kv3 = Kst[dd * 65 + 4 * tx + 3];
            s[0][0] += qv0 * kv0; s[0][1] += qv0 * kv1; s[0][2] += qv0 * kv2; s[0][3] += qv0 * kv3;
            s[1][0] += qv1 * kv0; s[1][1] += qv1 * kv1; s[1][2] += qv1 * kv2; s[1][3] += qv1 * kv3;
            s[2][0] += qv2 * kv0; s[2][1] += qv2 * kv1; s[2][2] += qv2 * kv2; s[2][3] += qv2 * kv3;
            s[3][0] += qv3 * kv0; s[3][1] += qv3 * kv1; s[3][2] += qv3 * kv2; s[3][3] += qv3 * kv3;
        }

        // Online softmax: row reductions via shfl across the 16 tx lanes
        #pragma unroll
        for (int i = 0; i < 4; i++) {
            float tm = fmaxf(fmaxf(s[i][0], s[i][1]), fmaxf(s[i][2], s[i][3]));
            #pragma unroll
            for (int off = 8; off; off >>= 1)
                tm = fmaxf(tm, __shfl_xor_sync(0xffffffffu, tm, off));
            float mn = fmaxf(mrow[i], tm);
            float al = __expf(mrow[i] - mn);
            mrow[i] = mn;
            float rs = 0.f;
            #pragma unroll
            for (int j = 0; j < 4; j++) {
                s[i][j] = __expf(s[i][j] - mn);
                rs += s[i][j];
            }
            #pragma unroll
            for (int off = 8; off; off >>= 1)
                rs += __shfl_xor_sync(0xffffffffu, rs, off);
            lrow[i] = lrow[i] * al + rs;
            #pragma unroll
            for (int j = 0; j < 4; j++) {
                acc[i][j] *= al;
                Ps[(4 * ty + i) * 65 + 4 * tx + j] = s[i][j];
            }
        }
        __syncthreads();

        // acc += P @ V
        #pragma unroll 8
        for (int m = 0; m < 64; m++) {
            float p0 = Ps[(4 * ty + 0) * 65 + m];
            float p1 = Ps[(4 * ty + 1) * 65 + m];
            float p2 = Ps[(4 * ty + 2) * 65 + m];
            float p3 = Ps[(4 * ty + 3) * 65 + m];
            float4 vv = *(const float4*)&Vs[m * 64 + 4 * tx];
            acc[0][0] += p0 * vv.x; acc[0][1] += p0 * vv.y; acc[0][2] += p0 * vv.z; acc[0][3] += p0 * vv.w;
            acc[1][0] += p1 * vv.x; acc[1][1] += p1 * vv.y; acc[1][2] += p1 * vv.z; acc[1][3] += p1 * vv.w;
            acc[2][0] += p2 * vv.x; acc[2][1] += p2 * vv.y; acc[2][2] += p2 * vv.z; acc[2][3] += p2 * vv.w;
            acc[3][0] += p3 * vv.x; acc[3][1] += p3 * vv.y; acc[3][2] += p3 * vv.z; acc[3][3] += p3 * vv.w;
        }
    }

    // Normalize and write to g_x[b][c][n], c = d*H + h. float4 over n (rows i).
    const int b = bh >> 2, h = bh & 3;
    #pragma unroll
    for (int i = 0; i < 4; i++) lrow[i] = 1.f / lrow[i];
    #pragma unroll
    for (int j = 0; j < 4; j++) {
        int d = 4 * tx + j;
        int c = d * HH + h;
        float4 o4 = make_float4(acc[0][j] * lrow[0], acc[1][j] * lrow[1],
                                acc[2][j] * lrow[2], acc[3][j] * lrow[3]);
        *(float4*)&g_x[((size_t)b * DM + c) * NN + n0 + 4 * ty] = o4;
    }
}

// ---------------------------------------------------------------------------
// Output projection: d_out[b,o,n] = sum_c Wm[o,c]*g_x[b,c,n] + bm[o]
// ---------------------------------------------------------------------------
__global__ __launch_bounds__(256) void out_proj_kernel(
    const float* __restrict__ Wm, const float* __restrict__ bm,
    float* __restrict__ out)
{
    __shared__ float Wt[32 * 65];
    __shared__ float Xs[32 * 64];

    const int tx = threadIdx.x, ty = threadIdx.y;
    const int tid = ty * 16 + tx;
    const int b = blockIdx.z;
    const int o0 = blockIdx.y * 64;
    const int n0 = blockIdx.x * 64;
    const float* Xb = g_x + (size_t)b * DM * NN;

    float acc[4][4];
    #pragma unroll
    for (int i = 0; i < 4; i++)
        #pragma unroll
        for (int j = 0; j < 4; j++) acc[i][j] = 0.f;

    for (int k0 = 0; k0 < DM; k0 += 32) {
        #pragma unroll
        for (int it = 0; it < 2; it++) {
            int t = tid + it * 256;
            int o = t >> 3, kk4 = (t & 7) << 2;
            float4 w4 = *(const float4*)(Wm + (size_t)(o0 + o) * DM + k0 + kk4);
            Wt[(kk4 + 0) * 65 + o] = w4.x;
            Wt[(kk4 + 1) * 65 + o] = w4.y;
            Wt[(kk4 + 2) * 65 + o] = w4.z;
            Wt[(kk4 + 3) * 65 + o] = w4.w;
            int r = t >> 4, c4 = (t & 15) << 2;
            *(float4*)&Xs[r * 64 + c4] =
                *(const float4*)(Xb + (size_t)(k0 + r) * NN + n0 + c4);
        }
        __syncthreads();
        #pragma unroll 8
        for (int kk = 0; kk < 32; kk++) {
            float w0 = Wt[kk * 65 + 4 * ty + 0];
            float w1 = Wt[kk * 65 + 4 * ty + 1];
            float w2 = Wt[kk * 65 + 4 * ty + 2];
            float w3 = Wt[kk * 65 + 4 * ty + 3];
            float4 xv = *(const float4*)&Xs[kk * 64 + 4 * tx];
            acc[0][0] += w0 * xv.x; acc[0][1] += w0 * xv.y; acc[0][2] += w0 * xv.z; acc[0][3] += w0 * xv.w;
            acc[1][0] += w1 * xv.x; acc[1][1] += w1 * xv.y; acc[1][2] += w1 * xv.z; acc[1][3] += w1 * xv.w;
            acc[2][0] += w2 * xv.x; acc[2][1] += w2 * xv.y; acc[2][2] += w2 * xv.z; acc[2][3] += w2 * xv.w;
            acc[3][0] += w3 * xv.x; acc[3][1] += w3 * xv.y; acc[3][2] += w3 * xv.z; acc[3][3] += w3 * xv.w;
        }
        __syncthreads();
    }

    #pragma unroll
    for (int i = 0; i < 4; i++) {
        int c = o0 + 4 * ty + i;
        float bv_ = bm[c];
        float4 o4 = make_float4(acc[i][0] + bv_, acc[i][1] + bv_,
                                acc[i][2] + bv_, acc[i][3] + bv_);
        *(float4*)&out[((size_t)b * DM + c) * NN + n0 + 4 * tx] = o4;
    }
}

// ---------------------------------------------------------------------------
extern "C" void kernel_launch(void* const* d_in, const int* in_sizes, int n_in,
                              void* d_out, int out_size)
{
    const float* q_in = (const float*)d_in[0];
    const float* k_in = (const float*)d_in[1];
    const float* v_in = (const float*)d_in[2];
    const float* enc  = (const float*)d_in[3];
    const float* Wq   = (const float*)d_in[4];
    const float* bq   = (const float*)d_in[5];
    const float* Wk   = (const float*)d_in[6];
    const float* bk   = (const float*)d_in[7];
    const float* Wv   = (const float*)d_in[8];
    const float* bv   = (const float*)d_in[9];
    const float* Wm   = (const float*)d_in[10];
    const float* bm   = (const float*)d_in[11];
    float* out = (float*)d_out;

    dim3 blk(16, 16);

    qkv_proj_kernel<<<dim3(NN / 64, DM / 64, 3 * BB), blk>>>(
        q_in, k_in, v_in, Wq, bq, Wk, bk, Wv, bv);

    rope_kernel<<<(BB * HH * NN * 32) / 256, 256>>>(enc);

    cudaFuncSetAttribute(attn_kernel,
                         cudaFuncAttributeMaxDynamicSharedMemorySize,
                         ATTN_SMEM_BYTES);
    attn_kernel<<<dim3(NN / 64, BB * HH), blk, ATTN_SMEM_BYTES>>>();

    out_proj_kernel<<<dim3(NN / 64, DM / 64, BB), blk>>>(Wm, bm, out);
}

// round 2
// speedup vs baseline: 2.2339x; 2.2339x over previous
#include <cuda_runtime.h>

#define BB 4
#define DM 256
#define NN 2048
#define HH 4
#define HD 64

// Scratch (device globals — no runtime allocation allowed)
__device__ float g_q[BB * HH * NN * HD];   // [b*H+h][n][d]
__device__ float g_k[BB * HH * NN * HD];
__device__ float g_v[BB * HH * NN * HD];
__device__ float g_x[BB * DM * NN];        // attention out, [b][c][n], c = d*H+h

// ---------------------------------------------------------------------------
// QKV projection: out[c,n] = sum_i W[c,i]*x[b,i,n] + bias[c]
// ---------------------------------------------------------------------------
__global__ __launch_bounds__(256) void qkv_proj_kernel(
    const float* __restrict__ qin, const float* __restrict__ kin,
    const float* __restrict__ vin,
    const float* __restrict__ Wq, const float* __restrict__ bq,
    const float* __restrict__ Wk, const float* __restrict__ bk,
    const float* __restrict__ Wv, const float* __restrict__ bv)
{
    __shared__ float Wt[32 * 65];
    __shared__ float Xs[32 * 64];
    __shared__ float Stg[64 * 65];

    const int tx = threadIdx.x, ty = threadIdx.y;
    const int tid = ty * 16 + tx;
    const int z = blockIdx.z;
    const int which = z >> 2, b = z & 3;

    const float* X; const float* W; const float* bias; float* dst;
    if (which == 0)      { X = qin; W = Wq; bias = bq; dst = g_q; }
    else if (which == 1) { X = kin; W = Wk; bias = bk; dst = g_k; }
    else                 { X = vin; W = Wv; bias = bv; dst = g_v; }

    const int o0 = blockIdx.y * 64;
    const int n0 = blockIdx.x * 64;
    const float* Xb = X + (size_t)b * DM * NN;

    float acc[4][4];
    #pragma unroll
    for (int i = 0; i < 4; i++)
        #pragma unroll
        for (int j = 0; j < 4; j++) acc[i][j] = 0.f;

    for (int k0 = 0; k0 < DM; k0 += 32) {
        #pragma unroll
        for (int it = 0; it < 2; it++) {
            int t = tid + it * 256;
            int o = t >> 3, kk4 = (t & 7) << 2;
            float4 w4 = *(const float4*)(W + (size_t)(o0 + o) * DM + k0 + kk4);
            Wt[(kk4 + 0) * 65 + o] = w4.x;
            Wt[(kk4 + 1) * 65 + o] = w4.y;
            Wt[(kk4 + 2) * 65 + o] = w4.z;
            Wt[(kk4 + 3) * 65 + o] = w4.w;
            int r = t >> 4, c4 = (t & 15) << 2;
            *(float4*)&Xs[r * 64 + c4] =
                *(const float4*)(Xb + (size_t)(k0 + r) * NN + n0 + c4);
        }
        __syncthreads();
        #pragma unroll 8
        for (int kk = 0; kk < 32; kk++) {
            float w0 = Wt[kk * 65 + 4 * ty + 0];
            float w1 = Wt[kk * 65 + 4 * ty + 1];
            float w2 = Wt[kk * 65 + 4 * ty + 2];
            float w3 = Wt[kk * 65 + 4 * ty + 3];
            float4 xv = *(const float4*)&Xs[kk * 64 + 4 * tx];
            acc[0][0] += w0 * xv.x; acc[0][1] += w0 * xv.y; acc[0][2] += w0 * xv.z; acc[0][3] += w0 * xv.w;
            acc[1][0] += w1 * xv.x; acc[1][1] += w1 * xv.y; acc[1][2] += w1 * xv.z; acc[1][3] += w1 * xv.w;
            acc[2][0] += w2 * xv.x; acc[2][1] += w2 * xv.y; acc[2][2] += w2 * xv.z; acc[2][3] += w2 * xv.w;
            acc[3][0] += w3 * xv.x; acc[3][1] += w3 * xv.y; acc[3][2] += w3 * xv.z; acc[3][3] += w3 * xv.w;
        }
        __syncthreads();
    }

    #pragma unroll
    for (int i = 0; i < 4; i++) {
        float bv_ = bias[o0 + 4 * ty + i];
        #pragma unroll
        for (int j = 0; j < 4; j++)
            Stg[(4 * ty + i) * 65 + 4 * tx + j] = acc[i][j] + bv_;
    }
    __syncthreads();
    #pragma unroll
    for (int it = 0; it < 16; it++) {
        int t = tid + it * 256;
        int dl = t & 15;
        int nl = (t >> 4) & 63;
        int h  = t >> 10;
        float v = Stg[(dl * 4 + h) * 65 + nl];
        dst[(((size_t)(b * HH + h)) * NN + n0 + nl) * HD + (o0 >> 2) + dl] = v;
    }
}

// ---------------------------------------------------------------------------
// RoPE on q and k in-place
// ---------------------------------------------------------------------------
__global__ __launch_bounds__(256) void rope_kernel(const float* __restrict__ enc)
{
    int idx = blockIdx.x * blockDim.x + threadIdx.x;
    int p  = idx & 31;
    int n  = (idx >> 5) & (NN - 1);
    int bh = idx >> 16;

    float2 c2 = *(const float2*)(enc + (size_t)n * HD + 2 * p);
    float2 s2 = *(const float2*)(enc + (size_t)NN * HD + (size_t)n * HD + 2 * p);
    size_t base = ((size_t)bh * NN + n) * HD + 2 * p;

    float2 qv = *(float2*)(g_q + base);
    float2 kv = *(float2*)(g_k + base);
    float2 qo, ko;
    qo.x = qv.x * c2.x - qv.y * s2.x;
    qo.y = qv.y * c2.y + qv.x * s2.y;
    ko.x = kv.x * c2.x - kv.y * s2.x;
    ko.y = kv.y * c2.y + kv.x * s2.y;
    *(float2*)(g_q + base) = qo;
    *(float2*)(g_k + base) = ko;
}

// ---------------------------------------------------------------------------
// TF32 tensor-core flash attention.
// 256 threads / 8 warps, 128 q-rows per block (16/warp), KV tiles of 64.
// ---------------------------------------------------------------------------
#define KS_STR 68
#define VS_STR 72
#define PS_STR 68
#define ATTN_SMEM_BYTES ((64 * KS_STR + 64 * VS_STR + 128 * PS_STR) * 4)

__device__ __forceinline__ unsigned f2tf(float f) {
    unsigned u;
    asm("cvt.rna.tf32.f32 %0, %1;" : "=r"(u) : "f"(f));
    return u;
}

__device__ __forceinline__ void mma_tf32(float c[4], const unsigned a[4],
                                         unsigned b0, unsigned b1) {
    asm volatile(
        "mma.sync.aligned.m16n8k8.row.col.f32.tf32.tf32.f32 "
        "{%0,%1,%2,%3}, {%4,%5,%6,%7}, {%8,%9}, {%0,%1,%2,%3};"
        : "+f"(c[0]), "+f"(c[1]), "+f"(c[2]), "+f"(c[3])
        : "r"(a[0]), "r"(a[1]), "r"(a[2]), "r"(a[3]), "r"(b0), "r"(b1));
}

__global__ __launch_bounds__(256) void attn_kernel()
{
    extern __shared__ unsigned smu[];
    unsigned* Ks = smu;                              // [c][d] tf32
    unsigned* Vs = smu + 64 * KS_STR;                // [m][d] tf32
    unsigned* Ps = smu + 64 * KS_STR + 64 * VS_STR;  // [r][m] tf32, 128 rows

    const int tid  = threadIdx.x;
    const int w    = tid >> 5;
    const int lane = tid & 31;
    const int g    = lane >> 2;
    const int q    = lane & 3;
    const int bh   = blockIdx.y;
    const int n0   = blockIdx.x * 128;
    const int wr   = w * 16;
    const size_t base = (size_t)bh * NN * HD;

    // Persistent Q fragments (pre-scaled by 1/8)
    unsigned qa[8][4];
    {
        const float* Q0 = g_q + base + (size_t)(n0 + wr + g) * HD;
        const float* Q1 = Q0 + 8 * HD;
        #pragma unroll
        for (int kf = 0; kf < 8; kf++) {
            int c0 = kf * 8 + q;
            qa[kf][0] = f2tf(Q0[c0]     * 0.125f);
            qa[kf][1] = f2tf(Q1[c0]     * 0.125f);
            qa[kf][2] = f2tf(Q0[c0 + 4] * 0.125f);
            qa[kf][3] = f2tf(Q1[c0 + 4] * 0.125f);
        }
    }

    float o[8][4];
    #pragma unroll
    for (int nf = 0; nf < 8; nf++)
        #pragma unroll
        for (int j = 0; j < 4; j++) o[nf][j] = 0.f;
    float m0r = -1e30f, m1r = -1e30f, l0 = 0.f, l1 = 0.f;

    for (int kv = 0; kv < NN; kv += 64) {
        __syncthreads();
        #pragma unroll
        for (int it = 0; it < 4; it++) {
            int idx = tid + it * 256;
            int r = idx >> 4, c4 = (idx & 15) << 2;
            float4 k4 = *(const float4*)(g_k + base + (size_t)(kv + r) * HD + c4);
            unsigned* kd = Ks + r * KS_STR + c4;
            kd[0] = f2tf(k4.x); kd[1] = f2tf(k4.y);
            kd[2] = f2tf(k4.z); kd[3] = f2tf(k4.w);
            float4 v4 = *(const float4*)(g_v + base + (size_t)(kv + r) * HD + c4);
            unsigned* vd = Vs + r * VS_STR + c4;
            vd[0] = f2tf(v4.x); vd[1] = f2tf(v4.y);
            vd[2] = f2tf(v4.z); vd[3] = f2tf(v4.w);
        }
        __syncthreads();

        // S = Q K^T
        float s[8][4];
        #pragma unroll
        for (int nf = 0; nf < 8; nf++) {
            #pragma unroll
            for (int j = 0; j < 4; j++) s[nf][j] = 0.f;
            #pragma unroll
            for (int kf = 0; kf < 8; kf++) {
                const unsigned* kp = Ks + (nf * 8 + g) * KS_STR + kf * 8 + q;
                mma_tf32(s[nf], qa[kf], kp[0], kp[4]);
            }
        }

        // Online softmax
        float tm0 = -1e30f, tm1 = -1e30f;
        #pragma unroll
        for (int nf = 0; nf < 8; nf++) {
            tm0 = fmaxf(tm0, fmaxf(s[nf][0], s[nf][1]));
            tm1 = fmaxf(tm1, fmaxf(s[nf][2], s[nf][3]));
        }
        tm0 = fmaxf(tm0, __shfl_xor_sync(0xffffffffu, tm0, 1));
        tm0 = fmaxf(tm0, __shfl_xor_sync(0xffffffffu, tm0, 2));
        tm1 = fmaxf(tm1, __shfl_xor_sync(0xffffffffu, tm1, 1));
        tm1 = fmaxf(tm1, __shfl_xor_sync(0xffffffffu, tm1, 2));

        float mn0 = fmaxf(m0r, tm0), mn1 = fmaxf(m1r, tm1);
        float a0 = __expf(m0r - mn0), a1 = __expf(m1r - mn1);
        m0r = mn0; m1r = mn1;

        float rs0 = 0.f, rs1 = 0.f;
        #pragma unroll
        for (int nf = 0; nf < 8; nf++) {
            s[nf][0] = __expf(s[nf][0] - mn0);
            s[nf][1] = __expf(s[nf][1] - mn0);
            s[nf][2] = __expf(s[nf][2] - mn1);
            s[nf][3] = __expf(s[nf][3] - mn1);
            rs0 += s[nf][0] + s[nf][1];
            rs1 += s[nf][2] + s[nf][3];
        }
        rs0 += __shfl_xor_sync(0xffffffffu, rs0, 1);
        rs0 += __shfl_xor_sync(0xffffffffu, rs0, 2);
        rs1 += __shfl_xor_sync(0xffffffffu, rs1, 1);
        rs1 += __shfl_xor_sync(0xffffffffu, rs1, 2);
        l0 = l0 * a0 + rs0;
        l1 = l1 * a1 + rs1;

        #pragma unroll
        for (int nf = 0; nf < 8; nf++) {
            o[nf][0] *= a0; o[nf][1] *= a0;
            o[nf][2] *= a1; o[nf][3] *= a1;
        }

        // Stage P (warp-private rows; only __syncwarp needed)
        #pragma unroll
        for (int nf = 0; nf < 8; nf++) {
            unsigned* p0 = Ps + (wr + g) * PS_STR + nf * 8 + 2 * q;
            p0[0] = f2tf(s[nf][0]); p0[1] = f2tf(s[nf][1]);
            unsigned* p1 = p0 + 8 * PS_STR;
            p1[0] = f2tf(s[nf][2]); p1[1] = f2tf(s[nf][3]);
        }
        __syncwarp();

        // O += P @ V  (kf outer: 4 live A regs)
        #pragma unroll
        for (int kf = 0; kf < 8; kf++) {
            unsigned pa[4];
            const unsigned* pp = Ps + (wr + g) * PS_STR + kf * 8 + q;
            pa[0] = pp[0];
            pa[1] = pp[8 * PS_STR];
            pa[2] = pp[4];
            pa[3] = pp[8 * PS_STR + 4];
            #pragma unroll
            for (int nf = 0; nf < 8; nf++) {
                const unsigned* vp = Vs + (kf * 8 + q) * VS_STR + nf * 8 + g;
                mma_tf32(o[nf], pa, vp[0], vp[4 * VS_STR]);
            }
        }
    }

    // Epilogue: normalize, write g_x[b][c][n] with c = d*H + h
    const int b = bh >> 2, h = bh & 3;
    float il0 = 1.f / l0, il1 = 1.f / l1;
    #pragma unroll
    for (int nf = 0; nf < 8; nf++) {
        #pragma unroll
        for (int j = 0; j < 2; j++) {
            int d = nf * 8 + 2 * q + j;
            int c = d * HH + h;
            size_t rowbase = ((size_t)b * DM + c) * NN + n0 + wr + g;
            g_x[rowbase]     = o[nf][j]     * il0;
            g_x[rowbase + 8] = o[nf][2 + j] * il1;
        }
    }
}

// ---------------------------------------------------------------------------
// Output projection
// ---------------------------------------------------------------------------
__global__ __launch_bounds__(256) void out_proj_kernel(
    const float* __restrict__ Wm, const float* __restrict__ bm,
    float* __restrict__ out)
{
    __shared__ float Wt[32 * 65];
    __shared__ float Xs[32 * 64];

    const int tx = threadIdx.x, ty = threadIdx.y;
    const int tid = ty * 16 + tx;
    const int b = blockIdx.z;
    const int o0 = blockIdx.y * 64;
    const int n0 = blockIdx.x * 64;
    const float* Xb = g_x + (size_t)b * DM * NN;

    float acc[4][4];
    #pragma unroll
    for (int i = 0; i < 4; i++)
        #pragma unroll
        for (int j = 0; j < 4; j++) acc[i][j] = 0.f;

    for (int k0 = 0; k0 < DM; k0 += 32) {
        #pragma unroll
        for (int it = 0; it < 2; it++) {
            int t = tid + it * 256;
            int o = t >> 3, kk4 = (t & 7) << 2;
            float4 w4 = *(const float4*)(Wm + (size_t)(o0 + o) * DM + k0 + kk4);
            Wt[(kk4 + 0) * 65 + o] = w4.x;
            Wt[(kk4 + 1) * 65 + o] = w4.y;
            Wt[(kk4 + 2) * 65 + o] = w4.z;
            Wt[(kk4 + 3) * 65 + o] = w4.w;
            int r = t >> 4, c4 = (t & 15) << 2;
            *(float4*)&Xs[r * 64 + c4] =
                *(const float4*)(Xb + (size_t)(k0 + r) * NN + n0 + c4);
        }
        __syncthreads();
        #pragma unroll 8
        for (int kk = 0; kk < 32; kk++) {
            float w0 = Wt[kk * 65 + 4 * ty + 0];
            float w1 = Wt[kk * 65 + 4 * ty + 1];
            float w2 = Wt[kk * 65 + 4 * ty + 2];
            float w3 = Wt[kk * 65 + 4 * ty + 3];
            float4 xv = *(const float4*)&Xs[kk * 64 + 4 * tx];
            acc[0][0] += w0 * xv.x; acc[0][1] += w0 * xv.y; acc[0][2] += w0 * xv.z; acc[0][3] += w0 * xv.w;
            acc[1][0] += w1 * xv.x; acc[1][1] += w1 * xv.y; acc[1][2] += w1 * xv.z; acc[1][3] += w1 * xv.w;
            acc[2][0] += w2 * xv.x; acc[2][1] += w2 * xv.y; acc[2][2] += w2 * xv.z; acc[2][3] += w2 * xv.w;
            acc[3][0] += w3 * xv.x; acc[3][1] += w3 * xv.y; acc[3][2] += w3 * xv.z; acc[3][3] += w3 * xv.w;
        }
        __syncthreads();
    }

    #pragma unroll
    for (int i = 0; i < 4; i++) {
        int c = o0 + 4 * ty + i;
        float bv_ = bm[c];
        float4 o4 = make_float4(acc[i][0] + bv_, acc[i][1] + bv_,
                                acc[i][2] + bv_, acc[i][3] + bv_);
        *(float4*)&out[((size_t)b * DM + c) * NN + n0 + 4 * tx] = o4;
    }
}

// ---------------------------------------------------------------------------
extern "C" void kernel_launch(void* const* d_in, const int* in_sizes, int n_in,
                              void* d_out, int out_size)
{
    const float* q_in = (const float*)d_in[0];
    const float* k_in = (const float*)d_in[1];
    const float* v_in = (const float*)d_in[2];
    const float* enc  = (const float*)d_in[3];
    const float* Wq   = (const float*)d_in[4];
    const float* bq   = (const float*)d_in[5];
    const float* Wk   = (const float*)d_in[6];
    const float* bk   = (const float*)d_in[7];
    const float* Wv   = (const float*)d_in[8];
    const float* bv   = (const float*)d_in[9];
    const float* Wm   = (const float*)d_in[10];
    const float* bm   = (const float*)d_in[11];
    float* out = (float*)d_out;

    dim3 blk(16, 16);

    qkv_proj_kernel<<<dim3(NN / 64, DM / 64, 3 * BB), blk>>>(
        q_in, k_in, v_in, Wq, bq, Wk, bk, Wv, bv);

    rope_kernel<<<(BB * HH * NN * 32) / 256, 256>>>(enc);

    cudaFuncSetAttribute(attn_kernel,
                         cudaFuncAttributeMaxDynamicSharedMemorySize,
                         ATTN_SMEM_BYTES);
    attn_kernel<<<dim3(NN / 128, BB * HH), 256, ATTN_SMEM_BYTES>>>();

    out_proj_kernel<<<dim3(NN / 64, DM / 64, BB), blk>>>(Wm, bm, out);
}

// round 3
// speedup vs baseline: 2.5776x; 1.1539x over previous
#include <cuda_runtime.h>

#define BB 4
#define DM 256
#define NN 2048
#define HH 4
#define HD 64

// Scratch (device globals — no runtime allocation allowed)
__device__ float g_q[BB * HH * NN * HD];   // [b*H+h][n][d]  (tf32-rounded, x0.125 after rope)
__device__ float g_k[BB * HH * NN * HD];   // tf32-rounded after rope
__device__ float g_v[BB * HH * NN * HD];   // tf32-rounded
__device__ float g_x[BB * DM * NN];        // attention out, [b][c][n], c = d*H+h

// ---------------------------------------------------------------------------
// helpers
// ---------------------------------------------------------------------------
__device__ __forceinline__ unsigned f2tf(float f) {
    unsigned u;
    asm("cvt.rna.tf32.f32 %0, %1;" : "=r"(u) : "f"(f));
    return u;
}

__device__ __forceinline__ void split_tf32(float x, unsigned& hi, unsigned& lo) {
    asm("cvt.rna.tf32.f32 %0, %1;" : "=r"(hi) : "f"(x));
    float r = x - __uint_as_float(hi);
    asm("cvt.rna.tf32.f32 %0, %1;" : "=r"(lo) : "f"(r));
}

__device__ __forceinline__ void mma_tf32(float c[4], const unsigned a[4],
                                         unsigned b0, unsigned b1) {
    asm volatile(
        "mma.sync.aligned.m16n8k8.row.col.f32.tf32.tf32.f32 "
        "{%0,%1,%2,%3}, {%4,%5,%6,%7}, {%8,%9}, {%0,%1,%2,%3};"
        : "+f"(c[0]), "+f"(c[1]), "+f"(c[2]), "+f"(c[3])
        : "r"(a[0]), "r"(a[1]), "r"(a[2]), "r"(a[3]), "r"(b0), "r"(b1));
}

// ---------------------------------------------------------------------------
// TF32-MMA projection (3-term split for ~fp32 accuracy).
// Y[o,n] = sum_k W[o,k] X[k,n] + bias[o].  BM=128, BN=128, BK=16.
// 8 warps: wm in {0,1} (64 rows each), wn in {0..3} (32 cols each).
// ---------------------------------------------------------------------------
#define PSTR 20      // smem row stride (floats): 20g+q distinct mod 32 -> conflict-free

struct ProjFrags {
    float c[4][4][4];
};

// mainloop shared by both projection kernels
__device__ __forceinline__ void proj_mainloop(
    const float* __restrict__ W, const float* __restrict__ Xb,
    int o0, int n0, unsigned* psm, float c[4][4][4])
{
    unsigned* Whi = psm;
    unsigned* Wlo = psm + 128 * PSTR;
    unsigned* Xhi = psm + 2 * 128 * PSTR;
    unsigned* Xlo = psm + 3 * 128 * PSTR;

    const int tid = threadIdx.x;
    const int w = tid >> 5, lane = tid & 31, g = lane >> 2, q = lane & 3;
    const int wm = w & 1, wn = w >> 1;

    for (int k0 = 0; k0 < DM; k0 += 16) {
        __syncthreads();
        // ---- W tile: 128 rows x 16 k (row-major, k contiguous) ----
        {
            int r = tid >> 1, hf = tid & 1;
            const float* wp = W + (size_t)(o0 + r) * DM + k0 + hf * 8;
            float4 wa = *(const float4*)wp;
            float4 wb = *(const float4*)(wp + 4);
            uint4 th, tl;
            split_tf32(wa.x, th.x, tl.x); split_tf32(wa.y, th.y, tl.y);
            split_tf32(wa.z, th.z, tl.z); split_tf32(wa.w, th.w, tl.w);
            *(uint4*)&Whi[r * PSTR + hf * 8] = th;
            *(uint4*)&Wlo[r * PSTR + hf * 8] = tl;
            split_tf32(wb.x, th.x, tl.x); split_tf32(wb.y, th.y, tl.y);
            split_tf32(wb.z, th.z, tl.z); split_tf32(wb.w, th.w, tl.w);
            *(uint4*)&Whi[r * PSTR + hf * 8 + 4] = th;
            *(uint4*)&Wlo[r * PSTR + hf * 8 + 4] = tl;
        }
        // ---- X tile: 16 k x 128 n, transposed into [n][k] ----
        #pragma unroll
        for (int it = 0; it < 2; it++) {
            int idx = tid + it * 256;
            int kk = idx & 15, ng = idx >> 4;
            const float* xp = Xb + (size_t)(k0 + kk) * NN + n0 + ng * 4;
            float4 xv = *(const float4*)xp;
            unsigned h, l;
            split_tf32(xv.x, h, l); Xhi[(ng*4+0)*PSTR + kk] = h; Xlo[(ng*4+0)*PSTR + kk] = l;
            split_tf32(xv.y, h, l); Xhi[(ng*4+1)*PSTR + kk] = h; Xlo[(ng*4+1)*PSTR + kk] = l;
            split_tf32(xv.z, h, l); Xhi[(ng*4+2)*PSTR + kk] = h; Xlo[(ng*4+2)*PSTR + kk] = l;
            split_tf32(xv.w, h, l); Xhi[(ng*4+3)*PSTR + kk] = h; Xlo[(ng*4+3)*PSTR + kk] = l;
        }
        __syncthreads();

        #pragma unroll
        for (int ks = 0; ks < 2; ks++) {
            unsigned ah[4][4], al[4][4];
            #pragma unroll
            for (int mf = 0; mf < 4; mf++) {
                int row = wm * 64 + mf * 16 + g;
                const unsigned* ph = Whi + row * PSTR + ks * 8 + q;
                ah[mf][0] = ph[0];          ah[mf][2] = ph[4];
                ah[mf][1] = ph[8 * PSTR];   ah[mf][3] = ph[8 * PSTR + 4];
                const unsigned* pl = Wlo + row * PSTR + ks * 8 + q;
                al[mf][0] = pl[0];          al[mf][2] = pl[4];
                al[mf][1] = pl[8 * PSTR];   al[mf][3] = pl[8 * PSTR + 4];
            }
            #pragma unroll
            for (int nf = 0; nf < 4; nf++) {
                int col = wn * 32 + nf * 8 + g;
                const unsigned* ph = Xhi + col * PSTR + ks * 8 + q;
                unsigned bh0 = ph[0], bh1 = ph[4];
                const unsigned* pl = Xlo + col * PSTR + ks * 8 + q;
                unsigned bl0 = pl[0], bl1 = pl[4];
                #pragma unroll
                for (int mf = 0; mf < 4; mf++) {
                    mma_tf32(c[mf][nf], ah[mf], bh0, bh1);
                    mma_tf32(c[mf][nf], ah[mf], bl0, bl1);
                    mma_tf32(c[mf][nf], al[mf], bh0, bh1);
                }
            }
        }
    }
}

// qkv projection: writes [bh][n][d] layout via staged transpose epilogue
__global__ __launch_bounds__(256) void qkv_proj_mma(
    const float* __restrict__ qin, const float* __restrict__ kin,
    const float* __restrict__ vin,
    const float* __restrict__ Wq, const float* __restrict__ bq,
    const float* __restrict__ Wk, const float* __restrict__ bk,
    const float* __restrict__ Wv, const float* __restrict__ bv)
{
    __shared__ unsigned psm[4 * 128 * PSTR];   // 40 KB, reused as Stg in epilogue

    const int tid = threadIdx.x;
    const int w = tid >> 5, lane = tid & 31, g = lane >> 2, q = lane & 3;
    const int wm = w & 1, wn = w >> 1;
    const int z = blockIdx.z;
    const int which = z >> 2, b = z & 3;

    const float* X; const float* W; const float* bias; float* dst;
    if (which == 0)      { X = qin; W = Wq; bias = bq; dst = g_q; }
    else if (which == 1) { X = kin; W = Wk; bias = bk; dst = g_k; }
    else                 { X = vin; W = Wv; bias = bv; dst = g_v; }

    const int o0 = blockIdx.y * 128;
    const int n0 = blockIdx.x * 128;
    const float* Xb = X + (size_t)b * DM * NN;

    float c[4][4][4];
    #pragma unroll
    for (int i = 0; i < 4; i++)
        #pragma unroll
        for (int j = 0; j < 4; j++)
            #pragma unroll
            for (int k = 0; k < 4; k++) c[i][j][k] = 0.f;

    proj_mainloop(W, Xb, o0, n0, psm, c);

    // Epilogue: 4 rounds of 32-n slices. Stage as Stg[n][h*32 + d_local].
    float* Stg = (float*)psm;                  // [32][132]
    const int d0 = o0 >> 2;
    #pragma unroll
    for (int r = 0; r < 4; r++) {
        __syncthreads();
        if (wn == r) {
            #pragma unroll
            for (int mf = 0; mf < 4; mf++) {
                int olA = wm * 64 + mf * 16 + g;
                int olB = olA + 8;
                int colA = (olA & 3) * 32 + (olA >> 2);
                int colB = (olB & 3) * 32 + (olB >> 2);
                #pragma unroll
                for (int nf = 0; nf < 4; nf++) {
                    int nl = nf * 8 + 2 * q;
                    Stg[nl * 132 + colA]       = c[mf][nf][0];
                    Stg[(nl + 1) * 132 + colA] = c[mf][nf][1];
                    Stg[nl * 132 + colB]       = c[mf][nf][2];
                    Stg[(nl + 1) * 132 + colB] = c[mf][nf][3];
                }
            }
        }
        __syncthreads();
        int c4 = tid & 31;
        int h  = c4 >> 3;
        int dl = (c4 & 7) * 4;
        #pragma unroll
        for (int p = 0; p < 4; p++) {
            int nl = (tid >> 5) + p * 8;
            float4 v = *(float4*)&Stg[nl * 132 + c4 * 4];
            v.x += bias[(d0 + dl + 0) * 4 + h];
            v.y += bias[(d0 + dl + 1) * 4 + h];
            v.z += bias[(d0 + dl + 2) * 4 + h];
            v.w += bias[(d0 + dl + 3) * 4 + h];
            int gn = n0 + r * 32 + nl;
            *(float4*)&dst[(((size_t)(b * HH + h)) * NN + gn) * HD + d0 + dl] = v;
        }
    }
}

// output projection: plain [b][o][n] writes
__global__ __launch_bounds__(256) void out_proj_mma(
    const float* __restrict__ Wm, const float* __restrict__ bm,
    float* __restrict__ out)
{
    __shared__ unsigned psm[4 * 128 * PSTR];

    const int tid = threadIdx.x;
    const int w = tid >> 5, lane = tid & 31, g = lane >> 2, q = lane & 3;
    const int wm = w & 1, wn = w >> 1;
    const int b = blockIdx.z;
    const int o0 = blockIdx.y * 128;
    const int n0 = blockIdx.x * 128;
    const float* Xb = g_x + (size_t)b * DM * NN;

    float c[4][4][4];
    #pragma unroll
    for (int i = 0; i < 4; i++)
        #pragma unroll
        for (int j = 0; j < 4; j++)
            #pragma unroll
            for (int k = 0; k < 4; k++) c[i][j][k] = 0.f;

    proj_mainloop(Wm, Xb, o0, n0, psm, c);

    #pragma unroll
    for (int mf = 0; mf < 4; mf++) {
        int o = o0 + wm * 64 + mf * 16 + g;
        float bv0 = bm[o], bv1 = bm[o + 8];
        #pragma unroll
        for (int nf = 0; nf < 4; nf++) {
            int gn = n0 + wn * 32 + nf * 8 + 2 * q;
            float2 p0 = make_float2(c[mf][nf][0] + bv0, c[mf][nf][1] + bv0);
            *(float2*)&out[((size_t)b * DM + o) * NN + gn] = p0;
            float2 p1 = make_float2(c[mf][nf][2] + bv1, c[mf][nf][3] + bv1);
            *(float2*)&out[((size_t)b * DM + o + 8) * NN + gn] = p1;
        }
    }
}

// ---------------------------------------------------------------------------
// RoPE + tf32 pre-rounding: q (x0.125), k rotated+rounded; v rounded.
// ---------------------------------------------------------------------------
__global__ __launch_bounds__(256) void rope_kernel(const float* __restrict__ enc)
{
    int idx = blockIdx.x * blockDim.x + threadIdx.x;
    int p  = idx & 31;
    int n  = (idx >> 5) & (NN - 1);
    int bh = idx >> 16;

    float2 c2 = *(const float2*)(enc + (size_t)n * HD + 2 * p);
    float2 s2 = *(const float2*)(enc + (size_t)NN * HD + (size_t)n * HD + 2 * p);
    size_t base = ((size_t)bh * NN + n) * HD + 2 * p;

    float2 qv = *(float2*)(g_q + base);
    float2 kv = *(float2*)(g_k + base);
    float2 vv = *(float2*)(g_v + base);
    float2 qo, ko;
    qo.x = (qv.x * c2.x - qv.y * s2.x) * 0.125f;
    qo.y = (qv.y * c2.y + qv.x * s2.y) * 0.125f;
    ko.x = kv.x * c2.x - kv.y * s2.x;
    ko.y = kv.y * c2.y + kv.x * s2.y;
    qo.x = __uint_as_float(f2tf(qo.x));
    qo.y = __uint_as_float(f2tf(qo.y));
    ko.x = __uint_as_float(f2tf(ko.x));
    ko.y = __uint_as_float(f2tf(ko.y));
    vv.x = __uint_as_float(f2tf(vv.x));
    vv.y = __uint_as_float(f2tf(vv.y));
    *(float2*)(g_q + base) = qo;
    *(float2*)(g_k + base) = ko;
    *(float2*)(g_v + base) = vv;
}

// ---------------------------------------------------------------------------
// TF32 tensor-core flash attention.
// 256 threads / 8 warps, 128 q-rows per block (16/warp), KV tiles of 64.
// K smem: (d,d+4)-pair interleaved, row stride 72 -> LDS.64 B-frags, no conflicts.
// V smem: plain copy [m][d], stride 72. P: [r][m], stride 68.
// ---------------------------------------------------------------------------
#define KS_STR 72
#define VS_STR 72
#define PS_STR 68
#define ATTN_SMEM_BYTES ((64 * KS_STR + 64 * VS_STR + 128 * PS_STR) * 4)

__global__ __launch_bounds__(256) void attn_kernel()
{
    extern __shared__ unsigned smu[];
    unsigned* Ks = smu;                              // [c][interleaved d]
    unsigned* Vs = smu + 64 * KS_STR;                // [m][d]
    unsigned* Ps = smu + 64 * KS_STR + 64 * VS_STR;  // [r][m], 128 rows

    const int tid  = threadIdx.x;
    const int w    = tid >> 5;
    const int lane = tid & 31;
    const int g    = lane >> 2;
    const int q    = lane & 3;
    const int bh   = blockIdx.y;
    const int n0   = blockIdx.x * 128;
    const int wr   = w * 16;
    const size_t base = (size_t)bh * NN * HD;

    // Persistent Q fragments (already tf32-rounded & scaled in rope kernel)
    unsigned qa[8][4];
    {
        const float* Q0 = g_q + base + (size_t)(n0 + wr + g) * HD;
        const float* Q1 = Q0 + 8 * HD;
        #pragma unroll
        for (int kf = 0; kf < 8; kf++) {
            int c0 = kf * 8 + q;
            qa[kf][0] = __float_as_uint(Q0[c0]);
            qa[kf][1] = __float_as_uint(Q1[c0]);
            qa[kf][2] = __float_as_uint(Q0[c0 + 4]);
            qa[kf][3] = __float_as_uint(Q1[c0 + 4]);
        }
    }

    float o[8][4];
    #pragma unroll
    for (int nf = 0; nf < 8; nf++)
        #pragma unroll
        for (int j = 0; j < 4; j++) o[nf][j] = 0.f;
    float m0r = -1e30f, m1r = -1e30f, l0 = 0.f, l1 = 0.f;

    for (int kv = 0; kv < NN; kv += 64) {
        __syncthreads();
        // Tile load: K interleaved pairs, V straight copy (pre-rounded)
        #pragma unroll
        for (int it = 0; it < 2; it++) {
            int idx = tid + it * 256;       // 0..511
            int r = idx >> 3;               // row 0..63
            int j = idx & 7;                // d8-group
            const float* kp = g_k + base + (size_t)(kv + r) * HD + j * 8;
            float4 klo = *(const float4*)kp;
            float4 khi = *(const float4*)(kp + 4);
            uint4 s0 = make_uint4(__float_as_uint(klo.x), __float_as_uint(khi.x),
                                  __float_as_uint(klo.y), __float_as_uint(khi.y));
            uint4 s1 = make_uint4(__float_as_uint(klo.z), __float_as_uint(khi.z),
                                  __float_as_uint(klo.w), __float_as_uint(khi.w));
            *(uint4*)&Ks[r * KS_STR + j * 8]     = s0;
            *(uint4*)&Ks[r * KS_STR + j * 8 + 4] = s1;
            const float* vp = g_v + base + (size_t)(kv + r) * HD + j * 8;
            *(uint4*)&Vs[r * VS_STR + j * 8]     = *(const uint4*)vp;
            *(uint4*)&Vs[r * VS_STR + j * 8 + 4] = *(const uint4*)(vp + 4);
        }
        __syncthreads();

        // S = Q K^T  (B-frags via LDS.64 from interleaved K)
        float s[8][4];
        #pragma unroll
        for (int nf = 0; nf < 8; nf++) {
            #pragma unroll
            for (int j = 0; j < 4; j++) s[nf][j] = 0.f;
            #pragma unroll
            for (int kf = 0; kf < 8; kf++) {
                uint2 bb = *(const uint2*)(Ks + (nf * 8 + g) * KS_STR + kf * 8 + 2 * q);
                mma_tf32(s[nf], qa[kf], bb.x, bb.y);
            }
        }

        // Online softmax
        float tm0 = -1e30f, tm1 = -1e30f;
        #pragma unroll
        for (int nf = 0; nf < 8; nf++) {
            tm0 = fmaxf(tm0, fmaxf(s[nf][0], s[nf][1]));
            tm1 = fmaxf(tm1, fmaxf(s[nf][2], s[nf][3]));
        }
        tm0 = fmaxf(tm0, __shfl_xor_sync(0xffffffffu, tm0, 1));
        tm0 = fmaxf(tm0, __shfl_xor_sync(0xffffffffu, tm0, 2));
        tm1 = fmaxf(tm1, __shfl_xor_sync(0xffffffffu, tm1, 1));
        tm1 = fmaxf(tm1, __shfl_xor_sync(0xffffffffu, tm1, 2));

        float mn0 = fmaxf(m0r, tm0), mn1 = fmaxf(m1r, tm1);
        float a0 = __expf(m0r - mn0), a1 = __expf(m1r - mn1);
        m0r = mn0; m1r = mn1;

        float rs0 = 0.f, rs1 = 0.f;
        #pragma unroll
        for (int nf = 0; nf < 8; nf++) {
            s[nf][0] = __expf(s[nf][0] - mn0);
            s[nf][1] = __expf(s[nf][1] - mn0);
            s[nf][2] = __expf(s[nf][2] - mn1);
            s[nf][3] = __expf(s[nf][3] - mn1);
            rs0 += s[nf][0] + s[nf][1];
            rs1 += s[nf][2] + s[nf][3];
        }
        rs0 += __shfl_xor_sync(0xffffffffu, rs0, 1);
        rs0 += __shfl_xor_sync(0xffffffffu, rs0, 2);
        rs1 += __shfl_xor_sync(0xffffffffu, rs1, 1);
        rs1 += __shfl_xor_sync(0xffffffffu, rs1, 2);
        l0 = l0 * a0 + rs0;
        l1 = l1 * a1 + rs1;

        #pragma unroll
        for (int nf = 0; nf < 8; nf++) {
            o[nf][0] *= a0; o[nf][1] *= a0;
            o[nf][2] *= a1; o[nf][3] *= a1;
        }

        // Stage P (warp-private rows)
        #pragma unroll
        for (int nf = 0; nf < 8; nf++) {
            unsigned* p0 = Ps + (wr + g) * PS_STR + nf * 8 + 2 * q;
            p0[0] = f2tf(s[nf][0]); p0[1] = f2tf(s[nf][1]);
            unsigned* p1 = p0 + 8 * PS_STR;
            p1[0] = f2tf(s[nf][2]); p1[1] = f2tf(s[nf][3]);
        }
        __syncwarp();

        // O += P @ V
        #pragma unroll
        for (int kf = 0; kf < 8; kf++) {
            unsigned pa[4];
            const unsigned* pp = Ps + (wr + g) * PS_STR + kf * 8 + q;
            pa[0] = pp[0];
            pa[1] = pp[8 * PS_STR];
            pa[2] = pp[4];
            pa[3] = pp[8 * PS_STR + 4];
            #pragma unroll
            for (int nf = 0; nf < 8; nf++) {
                const unsigned* vp = Vs + (kf * 8 + q) * VS_STR + nf * 8 + g;
                mma_tf32(o[nf], pa, vp[0], vp[4 * VS_STR]);
            }
        }
    }

    // Epilogue: normalize, write g_x[b][c][n] with c = d*H + h
    const int b = bh >> 2, h = bh & 3;
    float il0 = 1.f / l0, il1 = 1.f / l1;
    #pragma unroll
    for (int nf = 0; nf < 8; nf++) {
        #pragma unroll
        for (int j = 0; j < 2; j++) {
            int d = nf * 8 + 2 * q + j;
            int c = d * HH + h;
            size_t rowbase = ((size_t)b * DM + c) * NN + n0 + wr + g;
            g_x[rowbase]     = o[nf][j]     * il0;
            g_x[rowbase + 8] = o[nf][2 + j] * il1;
        }
    }
}

// ---------------------------------------------------------------------------
extern "C" void kernel_launch(void* const* d_in, const int* in_sizes, int n_in,
                              void* d_out, int out_size)
{
    const float* q_in = (const float*)d_in[0];
    const float* k_in = (const float*)d_in[1];
    const float* v_in = (const float*)d_in[2];
    const float* enc  = (const float*)d_in[3];
    const float* Wq   = (const float*)d_in[4];
    const float* bq   = (const float*)d_in[5];
    const float* Wk   = (const float*)d_in[6];
    const float* bk   = (const float*)d_in[7];
    const float* Wv   = (const float*)d_in[8];
    const float* bv   = (const float*)d_in[9];
    const float* Wm   = (const float*)d_in[10];
    const float* bm   = (const float*)d_in[11];
    float* out = (float*)d_out;

    qkv_proj_mma<<<dim3(NN / 128, DM / 128, 3 * BB), 256>>>(
        q_in, k_in, v_in, Wq, bq, Wk, bk, Wv, bv);

    rope_kernel<<<(BB * HH * NN * 32) / 256, 256>>>(enc);

    cudaFuncSetAttribute(attn_kernel,
                         cudaFuncAttributeMaxDynamicSharedMemorySize,
                         ATTN_SMEM_BYTES);
    attn_kernel<<<dim3(NN / 128, BB * HH), 256, ATTN_SMEM_BYTES>>>();

    out_proj_mma<<<dim3(NN / 128, DM / 128, BB), 256>>>(Wm, bm, out);
}

// round 4
// speedup vs baseline: 2.7029x; 1.0486x over previous
#include <cuda_runtime.h>

#define BB 4
#define DM 256
#define NN 2048
#define HH 4
#define HD 64

// Scratch (device globals — no runtime allocation allowed)
__device__ float g_q[BB * HH * NN * HD];   // [b*H+h][n][d]  (tf32-rounded, x0.125 after rope)
__device__ float g_k[BB * HH * NN * HD];   // tf32-rounded after rope
__device__ float g_v[BB * HH * NN * HD];   // tf32-rounded
__device__ float g_x[BB * DM * NN];        // attention out, [b][c][n], c = d*H+h

// ---------------------------------------------------------------------------
// helpers
// ---------------------------------------------------------------------------
__device__ __forceinline__ unsigned f2tf(float f) {
    unsigned u;
    asm("cvt.rna.tf32.f32 %0, %1;" : "=r"(u) : "f"(f));
    return u;
}

__device__ __forceinline__ void split_tf32(float x, unsigned& hi, unsigned& lo) {
    asm("cvt.rna.tf32.f32 %0, %1;" : "=r"(hi) : "f"(x));
    float r = x - __uint_as_float(hi);
    asm("cvt.rna.tf32.f32 %0, %1;" : "=r"(lo) : "f"(r));
}

__device__ __forceinline__ void mma_tf32(float c[4], const unsigned a[4],
                                         unsigned b0, unsigned b1) {
    asm volatile(
        "mma.sync.aligned.m16n8k8.row.col.f32.tf32.tf32.f32 "
        "{%0,%1,%2,%3}, {%4,%5,%6,%7}, {%8,%9}, {%0,%1,%2,%3};"
        : "+f"(c[0]), "+f"(c[1]), "+f"(c[2]), "+f"(c[3])
        : "r"(a[0]), "r"(a[1]), "r"(a[2]), "r"(a[3]), "r"(b0), "r"(b1));
}

// ---------------------------------------------------------------------------
// TF32-MMA projection, 3-term split, software-pipelined double buffer.
// Y[o,n] = sum_k W[o,k] X[k,n] + bias[o].  BM=128, BN=128, BK=16.
// ---------------------------------------------------------------------------
#define PSTR 20
#define PROJ_STAGE_U32 (4 * 128 * PSTR)
#define PROJ_SMEM_BYTES (2 * PROJ_STAGE_U32 * 4)   // 80 KB

__device__ __forceinline__ void proj_ldg(
    const float* __restrict__ W, const float* __restrict__ Xb,
    int o0, int n0, int k0, int tid,
    float4& wA, float4& wB, float4& xA, float4& xB)
{
    int r = tid >> 1, hf = tid & 1;
    const float* wp = W + (size_t)(o0 + r) * DM + k0 + hf * 8;
    wA = *(const float4*)wp;
    wB = *(const float4*)(wp + 4);
    int kk = tid & 15, ng = tid >> 4;
    xA = *(const float4*)(Xb + (size_t)(k0 + kk) * NN + n0 + ng * 4);
    xB = *(const float4*)(Xb + (size_t)(k0 + kk) * NN + n0 + (ng + 16) * 4);
}

__device__ __forceinline__ void proj_cvst(
    unsigned* st, int tid,
    const float4& wA, const float4& wB, const float4& xA, const float4& xB)
{
    unsigned* Whi = st;
    unsigned* Wlo = st + 128 * PSTR;
    unsigned* Xhi = st + 2 * 128 * PSTR;
    unsigned* Xlo = st + 3 * 128 * PSTR;

    int r = tid >> 1, hf = tid & 1;
    uint4 th, tl;
    split_tf32(wA.x, th.x, tl.x); split_tf32(wA.y, th.y, tl.y);
    split_tf32(wA.z, th.z, tl.z); split_tf32(wA.w, th.w, tl.w);
    *(uint4*)&Whi[r * PSTR + hf * 8] = th;
    *(uint4*)&Wlo[r * PSTR + hf * 8] = tl;
    split_tf32(wB.x, th.x, tl.x); split_tf32(wB.y, th.y, tl.y);
    split_tf32(wB.z, th.z, tl.z); split_tf32(wB.w, th.w, tl.w);
    *(uint4*)&Whi[r * PSTR + hf * 8 + 4] = th;
    *(uint4*)&Wlo[r * PSTR + hf * 8 + 4] = tl;

    int kk = tid & 15, ng = tid >> 4;
    unsigned h, l;
    split_tf32(xA.x, h, l); Xhi[(ng*4+0)*PSTR + kk] = h; Xlo[(ng*4+0)*PSTR + kk] = l;
    split_tf32(xA.y, h, l); Xhi[(ng*4+1)*PSTR + kk] = h; Xlo[(ng*4+1)*PSTR + kk] = l;
    split_tf32(xA.z, h, l); Xhi[(ng*4+2)*PSTR + kk] = h; Xlo[(ng*4+2)*PSTR + kk] = l;
    split_tf32(xA.w, h, l); Xhi[(ng*4+3)*PSTR + kk] = h; Xlo[(ng*4+3)*PSTR + kk] = l;
    int ng2 = ng + 16;
    split_tf32(xB.x, h, l); Xhi[(ng2*4+0)*PSTR + kk] = h; Xlo[(ng2*4+0)*PSTR + kk] = l;
    split_tf32(xB.y, h, l); Xhi[(ng2*4+1)*PSTR + kk] = h; Xlo[(ng2*4+1)*PSTR + kk] = l;
    split_tf32(xB.z, h, l); Xhi[(ng2*4+2)*PSTR + kk] = h; Xlo[(ng2*4+2)*PSTR + kk] = l;
    split_tf32(xB.w, h, l); Xhi[(ng2*4+3)*PSTR + kk] = h; Xlo[(ng2*4+3)*PSTR + kk] = l;
}

__device__ __forceinline__ void proj_mma_stage(
    const unsigned* st, int wm, int wn, int g, int q, float c[4][4][4])
{
    const unsigned* Whi = st;
    const unsigned* Wlo = st + 128 * PSTR;
    const unsigned* Xhi = st + 2 * 128 * PSTR;
    const unsigned* Xlo = st + 3 * 128 * PSTR;

    #pragma unroll
    for (int ks = 0; ks < 2; ks++) {
        unsigned ah[4][4], al[4][4];
        #pragma unroll
        for (int mf = 0; mf < 4; mf++) {
            int row = wm * 64 + mf * 16 + g;
            const unsigned* ph = Whi + row * PSTR + ks * 8 + q;
            ah[mf][0] = ph[0];          ah[mf][2] = ph[4];
            ah[mf][1] = ph[8 * PSTR];   ah[mf][3] = ph[8 * PSTR + 4];
            const unsigned* pl = Wlo + row * PSTR + ks * 8 + q;
            al[mf][0] = pl[0];          al[mf][2] = pl[4];
            al[mf][1] = pl[8 * PSTR];   al[mf][3] = pl[8 * PSTR + 4];
        }
        #pragma unroll
        for (int nf = 0; nf < 4; nf++) {
            int col = wn * 32 + nf * 8 + g;
            const unsigned* ph = Xhi + col * PSTR + ks * 8 + q;
            unsigned bh0 = ph[0], bh1 = ph[4];
            const unsigned* pl = Xlo + col * PSTR + ks * 8 + q;
            unsigned bl0 = pl[0], bl1 = pl[4];
            #pragma unroll
            for (int mf = 0; mf < 4; mf++) {
                mma_tf32(c[mf][nf], ah[mf], bh0, bh1);
                mma_tf32(c[mf][nf], ah[mf], bl0, bl1);
                mma_tf32(c[mf][nf], al[mf], bh0, bh1);
            }
        }
    }
}

__device__ __forceinline__ void proj_pipeline(
    const float* __restrict__ W, const float* __restrict__ Xb,
    int o0, int n0, unsigned* sm, float c[4][4][4])
{
    const int tid = threadIdx.x;
    const int w = tid >> 5, lane = tid & 31, g = lane >> 2, q = lane & 3;
    const int wm = w & 1, wn = w >> 1;
    unsigned* sm0 = sm;
    unsigned* sm1 = sm + PROJ_STAGE_U32;

    float4 wA, wB, xA, xB;
    proj_ldg(W, Xb, o0, n0, 0, tid, wA, wB, xA, xB);
    proj_cvst(sm0, tid, wA, wB, xA, xB);
    __syncthreads();

    #pragma unroll 1
    for (int it = 0; it < 16; it++) {
        unsigned* cur = (it & 1) ? sm1 : sm0;
        unsigned* nxt = (it & 1) ? sm0 : sm1;
        if (it < 15)
            proj_ldg(W, Xb, o0, n0, (it + 1) * 16, tid, wA, wB, xA, xB);
        proj_mma_stage(cur, wm, wn, g, q, c);
        if (it < 15)
            proj_cvst(nxt, tid, wA, wB, xA, xB);
        __syncthreads();
    }
}

// qkv projection: writes [bh][n][d] layout via staged transpose epilogue
__global__ __launch_bounds__(256) void qkv_proj_mma(
    const float* __restrict__ qin, const float* __restrict__ kin,
    const float* __restrict__ vin,
    const float* __restrict__ Wq, const float* __restrict__ bq,
    const float* __restrict__ Wk, const float* __restrict__ bk,
    const float* __restrict__ Wv, const float* __restrict__ bv)
{
    extern __shared__ unsigned psm[];

    const int tid = threadIdx.x;
    const int w = tid >> 5, lane = tid & 31, g = lane >> 2, q = lane & 3;
    const int wm = w & 1, wn = w >> 1;
    const int z = blockIdx.z;
    const int which = z >> 2, b = z & 3;

    const float* X; const float* W; const float* bias; float* dst;
    if (which == 0)      { X = qin; W = Wq; bias = bq; dst = g_q; }
    else if (which == 1) { X = kin; W = Wk; bias = bk; dst = g_k; }
    else                 { X = vin; W = Wv; bias = bv; dst = g_v; }

    const int o0 = blockIdx.y * 128;
    const int n0 = blockIdx.x * 128;
    const float* Xb = X + (size_t)b * DM * NN;

    float c[4][4][4];
    #pragma unroll
    for (int i = 0; i < 4; i++)
        #pragma unroll
        for (int j = 0; j < 4; j++)
            #pragma unroll
            for (int k = 0; k < 4; k++) c[i][j][k] = 0.f;

    proj_pipeline(W, Xb, o0, n0, psm, c);

    // Epilogue: 4 rounds of 32-n slices. Stage as Stg[n][h*32 + d_local].
    float* Stg = (float*)psm;                  // [32][132]
    const int d0 = o0 >> 2;
    #pragma unroll
    for (int r = 0; r < 4; r++) {
        __syncthreads();
        if (wn == r) {
            #pragma unroll
            for (int mf = 0; mf < 4; mf++) {
                int olA = wm * 64 + mf * 16 + g;
                int olB = olA + 8;
                int colA = (olA & 3) * 32 + (olA >> 2);
                int colB = (olB & 3) * 32 + (olB >> 2);
                #pragma unroll
                for (int nf = 0; nf < 4; nf++) {
                    int nl = nf * 8 + 2 * q;
                    Stg[nl * 132 + colA]       = c[mf][nf][0];
                    Stg[(nl + 1) * 132 + colA] = c[mf][nf][1];
                    Stg[nl * 132 + colB]       = c[mf][nf][2];
                    Stg[(nl + 1) * 132 + colB] = c[mf][nf][3];
                }
            }
        }
        __syncthreads();
        int c4 = tid & 31;
        int h  = c4 >> 3;
        int dl = (c4 & 7) * 4;
        #pragma unroll
        for (int p = 0; p < 4; p++) {
            int nl = (tid >> 5) + p * 8;
            float4 v = *(float4*)&Stg[nl * 132 + c4 * 4];
            v.x += bias[(d0 + dl + 0) * 4 + h];
            v.y += bias[(d0 + dl + 1) * 4 + h];
            v.z += bias[(d0 + dl + 2) * 4 + h];
            v.w += bias[(d0 + dl + 3) * 4 + h];
            int gn = n0 + r * 32 + nl;
            *(float4*)&dst[(((size_t)(b * HH + h)) * NN + gn) * HD + d0 + dl] = v;
        }
    }
}

// output projection: plain [b][o][n] writes
__global__ __launch_bounds__(256) void out_proj_mma(
    const float* __restrict__ Wm, const float* __restrict__ bm,
    float* __restrict__ out)
{
    extern __shared__ unsigned psm[];

    const int tid = threadIdx.x;
    const int w = tid >> 5, lane = tid & 31, g = lane >> 2, q = lane & 3;
    const int wm = w & 1, wn = w >> 1;
    const int b = blockIdx.z;
    const int o0 = blockIdx.y * 128;
    const int n0 = blockIdx.x * 128;
    const float* Xb = g_x + (size_t)b * DM * NN;

    float c[4][4][4];
    #pragma unroll
    for (int i = 0; i < 4; i++)
        #pragma unroll
        for (int j = 0; j < 4; j++)
            #pragma unroll
            for (int k = 0; k < 4; k++) c[i][j][k] = 0.f;

    proj_pipeline(Wm, Xb, o0, n0, psm, c);

    #pragma unroll
    for (int mf = 0; mf < 4; mf++) {
        int o = o0 + wm * 64 + mf * 16 + g;
        float bv0 = bm[o], bv1 = bm[o + 8];
        #pragma unroll
        for (int nf = 0; nf < 4; nf++) {
            int gn = n0 + wn * 32 + nf * 8 + 2 * q;
            float2 p0 = make_float2(c[mf][nf][0] + bv0, c[mf][nf][1] + bv0);
            *(float2*)&out[((size_t)b * DM + o) * NN + gn] = p0;
            float2 p1 = make_float2(c[mf][nf][2] + bv1, c[mf][nf][3] + bv1);
            *(float2*)&out[((size_t)b * DM + o + 8) * NN + gn] = p1;
        }
    }
}

// ---------------------------------------------------------------------------
// RoPE + tf32 pre-rounding: q (x0.125), k rotated+rounded; v rounded.
// ---------------------------------------------------------------------------
__global__ __launch_bounds__(256) void rope_kernel(const float* __restrict__ enc)
{
    int idx = blockIdx.x * blockDim.x + threadIdx.x;
    int p  = idx & 31;
    int n  = (idx >> 5) & (NN - 1);
    int bh = idx >> 16;

    float2 c2 = *(const float2*)(enc + (size_t)n * HD + 2 * p);
    float2 s2 = *(const float2*)(enc + (size_t)NN * HD + (size_t)n * HD + 2 * p);
    size_t base = ((size_t)bh * NN + n) * HD + 2 * p;

    float2 qv = *(float2*)(g_q + base);
    float2 kv = *(float2*)(g_k + base);
    float2 vv = *(float2*)(g_v + base);
    float2 qo, ko;
    qo.x = (qv.x * c2.x - qv.y * s2.x) * 0.125f;
    qo.y = (qv.y * c2.y + qv.x * s2.y) * 0.125f;
    ko.x = kv.x * c2.x - kv.y * s2.x;
    ko.y = kv.y * c2.y + kv.x * s2.y;
    qo.x = __uint_as_float(f2tf(qo.x));
    qo.y = __uint_as_float(f2tf(qo.y));
    ko.x = __uint_as_float(f2tf(ko.x));
    ko.y = __uint_as_float(f2tf(ko.y));
    vv.x = __uint_as_float(f2tf(vv.x));
    vv.y = __uint_as_float(f2tf(vv.y));
    *(float2*)(g_q + base) = qo;
    *(float2*)(g_k + base) = ko;
    *(float2*)(g_v + base) = vv;
}

// ---------------------------------------------------------------------------
// TF32 flash attention, 32 q-rows/warp, 8 warps (256 rows/block), KV tile 64.
// K and V B-fragments loaded once and shared across the two 16-row halves.
// ---------------------------------------------------------------------------
#define KS_STR 72
#define VS_STR 72
#define PS_STR 68
#define ATTN_SMEM_BYTES ((64 * KS_STR + 64 * VS_STR + 256 * PS_STR) * 4)

__global__ __launch_bounds__(256) void attn_kernel()
{
    extern __shared__ unsigned smu[];
    unsigned* Ks = smu;                              // [c][interleaved d]
    unsigned* Vs = smu + 64 * KS_STR;                // [m][d]
    unsigned* Ps = smu + 64 * KS_STR + 64 * VS_STR;  // [r][m], 256 rows

    const int tid  = threadIdx.x;
    const int w    = tid >> 5;
    const int lane = tid & 31;
    const int g    = lane >> 2;
    const int q    = lane & 3;
    const int bh   = blockIdx.y;
    const int n0   = blockIdx.x * 256;
    const int wr   = w * 32;
    const size_t base = (size_t)bh * NN * HD;

    // Persistent Q fragments for both 16-row halves
    unsigned qa[2][8][4];
    #pragma unroll
    for (int mf = 0; mf < 2; mf++) {
        const float* Q0 = g_q + base + (size_t)(n0 + wr + mf * 16 + g) * HD;
        const float* Q1 = Q0 + 8 * HD;
        #pragma unroll
        for (int kf = 0; kf < 8; kf++) {
            int c0 = kf * 8 + q;
            qa[mf][kf][0] = __float_as_uint(Q0[c0]);
            qa[mf][kf][1] = __float_as_uint(Q1[c0]);
            qa[mf][kf][2] = __float_as_uint(Q0[c0 + 4]);
            qa[mf][kf][3] = __float_as_uint(Q1[c0 + 4]);
        }
    }

    float o[2][8][4];
    #pragma unroll
    for (int mf = 0; mf < 2; mf++)
        #pragma unroll
        for (int nf = 0; nf < 8; nf++)
            #pragma unroll
            for (int j = 0; j < 4; j++) o[mf][nf][j] = 0.f;
    float mr[2][2], lr[2][2];
    #pragma unroll
    for (int mf = 0; mf < 2; mf++) {
        mr[mf][0] = -1e30f; mr[mf][1] = -1e30f;
        lr[mf][0] = 0.f;    lr[mf][1] = 0.f;
    }

    for (int kv = 0; kv < NN; kv += 64) {
        __syncthreads();
        // Tile load: K interleaved (d,d+4) pairs, V straight copy
        #pragma unroll
        for (int it = 0; it < 2; it++) {
            int idx = tid + it * 256;       // 0..511
            int r = idx >> 3;               // row 0..63
            int j = idx & 7;                // d8-group
            const float* kp = g_k + base + (size_t)(kv + r) * HD + j * 8;
            float4 klo = *(const float4*)kp;
            float4 khi = *(const float4*)(kp + 4);
            uint4 s0 = make_uint4(__float_as_uint(klo.x), __float_as_uint(khi.x),
                                  __float_as_uint(klo.y), __float_as_uint(khi.y));
            uint4 s1 = make_uint4(__float_as_uint(klo.z), __float_as_uint(khi.z),
                                  __float_as_uint(klo.w), __float_as_uint(khi.w));
            *(uint4*)&Ks[r * KS_STR + j * 8]     = s0;
            *(uint4*)&Ks[r * KS_STR + j * 8 + 4] = s1;
            const float* vp = g_v + base + (size_t)(kv + r) * HD + j * 8;
            *(uint4*)&Vs[r * VS_STR + j * 8]     = *(const uint4*)vp;
            *(uint4*)&Vs[r * VS_STR + j * 8 + 4] = *(const uint4*)(vp + 4);
        }
        __syncthreads();

        // S = Q K^T for both halves, sharing each K B-fragment
        float s[2][8][4];
        #pragma unroll
        for (int nf = 0; nf < 8; nf++) {
            #pragma unroll
            for (int j = 0; j < 4; j++) { s[0][nf][j] = 0.f; s[1][nf][j] = 0.f; }
            #pragma unroll
            for (int kf = 0; kf < 8; kf++) {
                uint2 bb = *(const uint2*)(Ks + (nf * 8 + g) * KS_STR + kf * 8 + 2 * q);
                mma_tf32(s[0][nf], qa[0][kf], bb.x, bb.y);
                mma_tf32(s[1][nf], qa[1][kf], bb.x, bb.y);
            }
        }

        // Online softmax per half
        #pragma unroll
        for (int mf = 0; mf < 2; mf++) {
            float tm0 = -1e30f, tm1 = -1e30f;
            #pragma unroll
            for (int nf = 0; nf < 8; nf++) {
                tm0 = fmaxf(tm0, fmaxf(s[mf][nf][0], s[mf][nf][1]));
                tm1 = fmaxf(tm1, fmaxf(s[mf][nf][2], s[mf][nf][3]));
            }
            tm0 = fmaxf(tm0, __shfl_xor_sync(0xffffffffu, tm0, 1));
            tm0 = fmaxf(tm0, __shfl_xor_sync(0xffffffffu, tm0, 2));
            tm1 = fmaxf(tm1, __shfl_xor_sync(0xffffffffu, tm1, 1));
            tm1 = fmaxf(tm1, __shfl_xor_sync(0xffffffffu, tm1, 2));

            float mn0 = fmaxf(mr[mf][0], tm0), mn1 = fmaxf(mr[mf][1], tm1);
            float a0 = __expf(mr[mf][0] - mn0), a1 = __expf(mr[mf][1] - mn1);
            mr[mf][0] = mn0; mr[mf][1] = mn1;

            float rs0 = 0.f, rs1 = 0.f;
            #pragma unroll
            for (int nf = 0; nf < 8; nf++) {
                s[mf][nf][0] = __expf(s[mf][nf][0] - mn0);
                s[mf][nf][1] = __expf(s[mf][nf][1] - mn0);
                s[mf][nf][2] = __expf(s[mf][nf][2] - mn1);
                s[mf][nf][3] = __expf(s[mf][nf][3] - mn1);
                rs0 += s[mf][nf][0] + s[mf][nf][1];
                rs1 += s[mf][nf][2] + s[mf][nf][3];
            }
            rs0 += __shfl_xor_sync(0xffffffffu, rs0, 1);
            rs0 += __shfl_xor_sync(0xffffffffu, rs0, 2);
            rs1 += __shfl_xor_sync(0xffffffffu, rs1, 1);
            rs1 += __shfl_xor_sync(0xffffffffu, rs1, 2);
            lr[mf][0] = lr[mf][0] * a0 + rs0;
            lr[mf][1] = lr[mf][1] * a1 + rs1;

            #pragma unroll
            for (int nf = 0; nf < 8; nf++) {
                o[mf][nf][0] *= a0; o[mf][nf][1] *= a0;
                o[mf][nf][2] *= a1; o[mf][nf][3] *= a1;
            }

            // Stage P half (warp-private rows)
            #pragma unroll
            for (int nf = 0; nf < 8; nf++) {
                unsigned* p0 = Ps + (wr + mf * 16 + g) * PS_STR + nf * 8 + 2 * q;
                p0[0] = f2tf(s[mf][nf][0]); p0[1] = f2tf(s[mf][nf][1]);
                unsigned* p1 = p0 + 8 * PS_STR;
                p1[0] = f2tf(s[mf][nf][2]); p1[1] = f2tf(s[mf][nf][3]);
            }
        }
        __syncwarp();

        // O += P @ V, sharing each V B-fragment across the two halves
        #pragma unroll
        for (int kf = 0; kf < 8; kf++) {
            unsigned pa[2][4];
            #pragma unroll
            for (int mf = 0; mf < 2; mf++) {
                const unsigned* pp = Ps + (wr + mf * 16 + g) * PS_STR + kf * 8 + q;
                pa[mf][0] = pp[0];
                pa[mf][1] = pp[8 * PS_STR];
                pa[mf][2] = pp[4];
                pa[mf][3] = pp[8 * PS_STR + 4];
            }
            #pragma unroll
            for (int nf = 0; nf < 8; nf++) {
                const unsigned* vp = Vs + (kf * 8 + q) * VS_STR + nf * 8 + g;
                unsigned b0 = vp[0], b1 = vp[4 * VS_STR];
                mma_tf32(o[0][nf], pa[0], b0, b1);
                mma_tf32(o[1][nf], pa[1], b0, b1);
            }
        }
    }

    // Epilogue: normalize, write g_x[b][c][n] with c = d*H + h
    const int b = bh >> 2, h = bh & 3;
    #pragma unroll
    for (int mf = 0; mf < 2; mf++) {
        float il0 = 1.f / lr[mf][0], il1 = 1.f / lr[mf][1];
        #pragma unroll
        for (int nf = 0; nf < 8; nf++) {
            #pragma unroll
            for (int j = 0; j < 2; j++) {
                int d = nf * 8 + 2 * q + j;
                int c = d * HH + h;
                size_t rowbase = ((size_t)b * DM + c) * NN + n0 + wr + mf * 16 + g;
                g_x[rowbase]     = o[mf][nf][j]     * il0;
                g_x[rowbase + 8] = o[mf][nf][2 + j] * il1;
            }
        }
    }
}

// ---------------------------------------------------------------------------
extern "C" void kernel_launch(void* const* d_in, const int* in_sizes, int n_in,
                              void* d_out, int out_size)
{
    const float* q_in = (const float*)d_in[0];
    const float* k_in = (const float*)d_in[1];
    const float* v_in = (const float*)d_in[2];
    const float* enc  = (const float*)d_in[3];
    const float* Wq   = (const float*)d_in[4];
    const float* bq   = (const float*)d_in[5];
    const float* Wk   = (const float*)d_in[6];
    const float* bk   = (const float*)d_in[7];
    const float* Wv   = (const float*)d_in[8];
    const float* bv   = (const float*)d_in[9];
    const float* Wm   = (const float*)d_in[10];
    const float* bm   = (const float*)d_in[11];
    float* out = (float*)d_out;

    cudaFuncSetAttribute(qkv_proj_mma,
                         cudaFuncAttributeMaxDynamicSharedMemorySize,
                         PROJ_SMEM_BYTES);
    cudaFuncSetAttribute(out_proj_mma,
                         cudaFuncAttributeMaxDynamicSharedMemorySize,
                         PROJ_SMEM_BYTES);
    cudaFuncSetAttribute(attn_kernel,
                         cudaFuncAttributeMaxDynamicSharedMemorySize,
                         ATTN_SMEM_BYTES);

    qkv_proj_mma<<<dim3(NN / 128, DM / 128, 3 * BB), 256, PROJ_SMEM_BYTES>>>(
        q_in, k_in, v_in, Wq, bq, Wk, bk, Wv, bv);

    rope_kernel<<<(BB * HH * NN * 32) / 256, 256>>>(enc);

    attn_kernel<<<dim3(NN / 256, BB * HH), 256, ATTN_SMEM_BYTES>>>();

    out_proj_mma<<<dim3(NN / 128, DM / 128, BB), 256, PROJ_SMEM_BYTES>>>(Wm, bm, out);
}